// round 15
// baseline (speedup 1.0000x reference)
#include <cuda_runtime.h>

// Problem shape (fixed by the reference)
#define BB 64
#define SS 2048
#define DD 256
#define TROWS 64                     // rows per ticket (contiguous, 64 KB)
#define TPB (SS / TROWS)             // 32 tickets per batch
#define NTILES (BB * TPB)            // 2048 tickets total
#define BATCH 8                      // in-flight float4 loads per thread
#define GRIDX 608                    // 152 SMs x occ 4 -> one exact wave

// Global scratch (statically zero-initialized; reset in-kernel each call so
// graph replays see a clean state).
__device__ float    g_sum [BB * DD];
__device__ unsigned g_maxo[BB * DD];   // order-preserving uint encoding
__device__ float    g_cnt [BB];
__device__ int      g_rows[BB];        // rows processed for b (arrival counter)
__device__ int      g_ticket;          // dynamic work counter
__device__ int      g_exit;            // CTAs done (last one resets counters)

__device__ __forceinline__ float neg_inf() { return __int_as_float(0xff800000); }

__device__ __forceinline__ unsigned f2o(float f) {
    unsigned u = __float_as_uint(f);
    return (u & 0x80000000u) ? ~u : (u | 0x80000000u);
}
__device__ __forceinline__ float o2f(unsigned u) {
    return __uint_as_float((u & 0x80000000u) ? (u & 0x7fffffffu) : ~u);
}
__device__ __forceinline__ int atom_add_acq_rel(int* addr, int v) {
    int old;
    asm volatile("atom.add.acq_rel.gpu.global.s32 %0, [%1], %2;"
                 : "=r"(old) : "l"(addr), "r"(v) : "memory");
    return old;
}

// Dynamic-ticket pooling: 608 CTAs pull 64-row tiles from a global counter.
// Work-conserving balance (+/- one tile per CTA), contiguous 64 KB locality,
// register accumulation across same-b tiles, REDG flush on b-change, inline
// finalize via row-count arrival. 256 threads: d4 = tid % 64 (float4 lane over
// D=256), sg = tid / 64 (4 rows in parallel; mask addresses warp-uniform).
__global__ void __launch_bounds__(256, 4)
pool_ticket(const float* __restrict__ feats,
            const float* __restrict__ mask,
            float* __restrict__ out) {
    const int tid = threadIdx.x;
    const int d4  = tid & 63;
    const int sg  = tid >> 6;

    __shared__ float4 s_sum[256];
    __shared__ float4 s_max[256];
    __shared__ float  s_cnt[4];
    __shared__ int    s_t;
    __shared__ int    s_last;

    float4 sum = make_float4(0.f, 0.f, 0.f, 0.f);
    float4 mx  = make_float4(neg_inf(), neg_inf(), neg_inf(), neg_inf());
    float  cnt = 0.f;

    int cur_b = -1;
    int rows_held = 0;

    // Flush accumulators for cur_b: REDG the partials (skip if identity), then
    // arrive rows_held on g_rows[cur_b]; whoever completes SS rows finalizes.
    auto flush = [&]() {
        s_sum[tid] = sum;
        s_max[tid] = mx;
        if (d4 == 0) s_cnt[sg] = cnt;
        __syncthreads();

        const float ctot = s_cnt[0] + s_cnt[1] + s_cnt[2] + s_cnt[3];
        if (tid < 64 && ctot > 0.f) {
            float4 a = s_sum[tid];
            float4 m = s_max[tid];
#pragma unroll
            for (int k = 1; k < 4; ++k) {
                float4 a2 = s_sum[tid + 64 * k];
                float4 m2 = s_max[tid + 64 * k];
                a.x += a2.x; a.y += a2.y; a.z += a2.z; a.w += a2.w;
                m.x = fmaxf(m.x, m2.x); m.y = fmaxf(m.y, m2.y);
                m.z = fmaxf(m.z, m2.z); m.w = fmaxf(m.w, m2.w);
            }
            const int dbase = cur_b * DD + tid * 4;
            atomicAdd(&g_sum[dbase + 0], a.x);
            atomicAdd(&g_sum[dbase + 1], a.y);
            atomicAdd(&g_sum[dbase + 2], a.z);
            atomicAdd(&g_sum[dbase + 3], a.w);
            atomicMax(&g_maxo[dbase + 0], f2o(m.x));
            atomicMax(&g_maxo[dbase + 1], f2o(m.y));
            atomicMax(&g_maxo[dbase + 2], f2o(m.z));
            atomicMax(&g_maxo[dbase + 3], f2o(m.w));
            if (tid == 0) atomicAdd(&g_cnt[cur_b], ctot);
        }
        // syncthreads orders every thread's REDGs before tid0's acq_rel arrive
        __syncthreads();
        if (tid == 0) {
            int prev = atom_add_acq_rel(&g_rows[cur_b], rows_held);
            s_last = (prev + rows_held == SS);
        }
        __syncthreads();
        if (s_last) {
            const int d = tid;  // 0..255
            float    fsum = __ldcg(&g_sum[cur_b * DD + d]);
            unsigned mo   = __ldcg(&g_maxo[cur_b * DD + d]);
            float    fcnt = __ldcg(&g_cnt[cur_b]);
            out[(size_t)cur_b * (2 * DD) + d]      = o2f(mo);
            out[(size_t)cur_b * (2 * DD) + DD + d] = fsum / fcnt;
            __stcg(&g_sum[cur_b * DD + d], 0.f);
            __stcg(&g_maxo[cur_b * DD + d], 0u);
            if (tid == 0) {
                __stcg(&g_cnt[cur_b], 0.f);
                __stcg(&g_rows[cur_b], 0);
            }
        }
        __syncthreads();   // protect smem reuse by the next ticket
        sum = make_float4(0.f, 0.f, 0.f, 0.f);
        mx  = make_float4(neg_inf(), neg_inf(), neg_inf(), neg_inf());
        cnt = 0.f;
        rows_held = 0;
    };

    for (;;) {
        if (tid == 0) s_t = atomicAdd(&g_ticket, 1);
        __syncthreads();
        const int t = s_t;
        __syncthreads();   // all read s_t before tid0's next write
        if (t >= NTILES) break;

        const int b  = t >> 5;            // t / TPB
        const int s0 = (t & (TPB - 1)) * TROWS;

        if (b != cur_b) {
            if (rows_held > 0) flush();
            cur_b = b;
        }

        const float4* __restrict__ p =
            reinterpret_cast<const float4*>(feats) +
            ((size_t)b * SS + s0 + sg) * 64 + d4;
        const float* __restrict__ mp = mask + (size_t)b * SS + s0 + sg;

#pragma unroll
        for (int k = 0; k < TROWS / 32; ++k) {   // 2 sub-batches of 32 rows
            float mbuf[BATCH];
#pragma unroll
            for (int j = 0; j < BATCH; ++j)
                mbuf[j] = __ldca(mp + k * 32 + j * 4);

            bool allv = true, anyv = false;
#pragma unroll
            for (int j = 0; j < BATCH; ++j) {
                const bool v = (mbuf[j] > 0.f);
                allv &= v;
                anyv |= v;
            }

            const float4* __restrict__ pk = p + (size_t)k * 32 * 64;
            if (allv) {
                float4 fbuf[BATCH];
#pragma unroll
                for (int j = 0; j < BATCH; ++j) fbuf[j] = __ldcs(pk + j * 4 * 64);
#pragma unroll
                for (int j = 0; j < BATCH; ++j) {
                    const float  m = mbuf[j];
                    const float4 f = fbuf[j];
                    cnt += m;
                    sum.x += f.x * m;  sum.y += f.y * m;
                    sum.z += f.z * m;  sum.w += f.w * m;
                    mx.x = fmaxf(mx.x, f.x);
                    mx.y = fmaxf(mx.y, f.y);
                    mx.z = fmaxf(mx.z, f.z);
                    mx.w = fmaxf(mx.w, f.w);
                }
            } else if (anyv) {
                // Boundary: per-row predicated loads (warp-uniform mask) —
                // zero wasted traffic, no select needed on valid rows.
#pragma unroll
                for (int j = 0; j < BATCH; ++j) {
                    const float m = mbuf[j];
                    if (m > 0.f) {
                        const float4 f = __ldcs(pk + j * 4 * 64);
                        cnt += m;
                        sum.x += f.x * m;  sum.y += f.y * m;
                        sum.z += f.z * m;  sum.w += f.w * m;
                        mx.x = fmaxf(mx.x, f.x);
                        mx.y = fmaxf(mx.y, f.y);
                        mx.z = fmaxf(mx.z, f.z);
                        mx.w = fmaxf(mx.w, f.w);
                    }
                }
            }
            // else: fully-masked sub-batch — no feats loads.
        }
        rows_held += TROWS;
    }

    if (rows_held > 0) flush();

    // Exit protocol: the last CTA out resets the shared counters for the next
    // graph replay (all ticket draws happen-before the final g_exit arrival).
    __syncthreads();
    if (tid == 0) {
        int prev = atom_add_acq_rel(&g_exit, 1);
        if (prev == GRIDX - 1) {
            __stcg(&g_ticket, 0);
            __stcg(&g_exit, 0);
        }
    }
}

extern "C" void kernel_launch(void* const* d_in, const int* in_sizes, int n_in,
                              void* d_out, int out_size) {
    const float* feats = (const float*)d_in[0];
    const float* mask  = (const float*)d_in[1];
    float* out = (float*)d_out;

    pool_ticket<<<GRIDX, 256>>>(feats, mask, out);
}

// round 16
// speedup vs baseline: 1.3282x; 1.3282x over previous
#include <cuda_runtime.h>

// Problem shape (fixed by the reference)
#define BB 64
#define SS 2048
#define DD 256
#define NSPLIT 16
#define NI (SS / NSPLIT)             // 128 strided row-indices per CTA
#define BATCH 4                      // in-flight float4 loads per thread
#define NSUB (NI / (4 * BATCH))      // 8 sub-batches of 16 indices

// Global scratch (statically zero-initialized; reset by the finalizing CTA each
// call so graph replays see a clean state).
__device__ float    g_sum [BB * DD];
__device__ unsigned g_maxo[BB * DD];   // order-preserving uint encoding
__device__ float    g_cnt [BB];
__device__ int      g_arrived[BB];

__device__ __forceinline__ float neg_inf() { return __int_as_float(0xff800000); }

__device__ __forceinline__ unsigned f2o(float f) {
    unsigned u = __float_as_uint(f);
    return (u & 0x80000000u) ? ~u : (u | 0x80000000u);
}
__device__ __forceinline__ float o2f(unsigned u) {
    return __uint_as_float((u & 0x80000000u) ? (u & 0x7fffffffu) : ~u);
}
__device__ __forceinline__ int arrive_acq_rel(int* addr) {
    int old;
    asm volatile("atom.add.acq_rel.gpu.global.s32 %0, [%1], 1;"
                 : "=r"(old) : "l"(addr) : "memory");
    return old;
}

// One CTA per (split, b). Rows assigned STRIDED: s = split + 16*i, i = 0..127,
// so for a prefix mask all 16 CTAs of batch b carry ~L_b/16 valid rows each —
// intrinsic balance. Validity in i-space is still a prefix: warp-uniform
// sub-batch gating (allv fast path / per-row predicated boundary / early exit)
// costs zero wasted feats traffic. BATCH=4 keeps regs <= 42 so SIX CTAs fit
// per SM (vs 4 before): the L1tex queue is the in-flight cap anyway, and the
// extra resident CTAs backfill dead/boundary CTAs and collapse the second
// wave (1024 CTAs / 912 slots = 1.12 waves). 256 threads: d4 = tid % 64,
// sg = tid / 64.
__global__ void __launch_bounds__(256, 6)
pool_strided6(const float* __restrict__ feats,
              const float* __restrict__ mask,
              float* __restrict__ out) {
    const int split = blockIdx.x;
    const int b     = blockIdx.y;
    const int tid   = threadIdx.x;
    const int d4    = tid & 63;
    const int sg    = tid >> 6;

    // Thread's first row: i = sg -> s = split + 16*sg; i-stride 4 -> s-stride 64.
    const float4* __restrict__ p =
        reinterpret_cast<const float4*>(feats) +
        ((size_t)b * SS + split + 16 * sg) * 64 + d4;
    const float* __restrict__ mp = mask + (size_t)b * SS + split + 16 * sg;

    float4 sum = make_float4(0.f, 0.f, 0.f, 0.f);
    float4 mx  = make_float4(neg_inf(), neg_inf(), neg_inf(), neg_inf());
    float  cnt = 0.f;

    // Prime the mask pipeline with sub-batch 0 (i-stride 4 => s-stride 64)
    float mbuf[BATCH];
#pragma unroll
    for (int j = 0; j < BATCH; ++j) mbuf[j] = __ldca(mp + j * 64);

    bool done = false;   // prefix: after an all-invalid sub-batch, all later are too
#pragma unroll
    for (int k = 0; k < NSUB; ++k) {
        if (done) break;

        bool allv = true, anyv = false;
#pragma unroll
        for (int j = 0; j < BATCH; ++j) {
            const bool v = (mbuf[j] > 0.f);
            allv &= v;
            anyv |= v;
        }

        // Prefetch next sub-batch's masks before touching feats
        float mnext[BATCH];
        if (k + 1 < NSUB) {
#pragma unroll
            for (int j = 0; j < BATCH; ++j)
                mnext[j] = __ldca(mp + (k + 1) * 16 * 16 + j * 64);
        }

        // Sub-batch k: i = 16k + 4j + sg -> row offset 16*(16k+4j) from base
        const float4* __restrict__ pk = p + (size_t)k * 16 * 16 * 64;
        if (allv) {
            // All rows valid: unconditional batched loads, select-free max.
            float4 fbuf[BATCH];
#pragma unroll
            for (int j = 0; j < BATCH; ++j) fbuf[j] = __ldcs(pk + (size_t)j * 64 * 64);
#pragma unroll
            for (int j = 0; j < BATCH; ++j) {
                const float  m = mbuf[j];
                const float4 f = fbuf[j];
                cnt += m;
                sum.x += f.x * m;  sum.y += f.y * m;
                sum.z += f.z * m;  sum.w += f.w * m;
                mx.x = fmaxf(mx.x, f.x);
                mx.y = fmaxf(mx.y, f.y);
                mx.z = fmaxf(mx.z, f.z);
                mx.w = fmaxf(mx.w, f.w);
            }
        } else if (anyv) {
            // Boundary: per-row predicated loads (warp-uniform mask) — zero
            // wasted feats traffic; valid rows need no select.
#pragma unroll
            for (int j = 0; j < BATCH; ++j) {
                const float m = mbuf[j];
                if (m > 0.f) {
                    const float4 f = __ldcs(pk + (size_t)j * 64 * 64);
                    cnt += m;
                    sum.x += f.x * m;  sum.y += f.y * m;
                    sum.z += f.z * m;  sum.w += f.w * m;
                    mx.x = fmaxf(mx.x, f.x);
                    mx.y = fmaxf(mx.y, f.y);
                    mx.z = fmaxf(mx.z, f.z);
                    mx.w = fmaxf(mx.w, f.w);
                }
            }
            done = true;   // prefix ended inside this sub-batch
        } else {
            done = true;   // fully past the prefix
        }

#pragma unroll
        for (int j = 0; j < BATCH; ++j) mbuf[j] = mnext[j];
    }

    // CTA-level reduce: 4 sg-groups -> 1 (64 float4 lanes remain)
    __shared__ float4 s_sum[256];
    __shared__ float4 s_max[256];
    __shared__ float  s_cnt[4];
    s_sum[tid] = sum;
    s_max[tid] = mx;
    if (d4 == 0) s_cnt[sg] = cnt;
    __syncthreads();

    if (tid < 64) {
        const float ctot = s_cnt[0] + s_cnt[1] + s_cnt[2] + s_cnt[3];
        if (ctot > 0.f) {   // dead CTAs contribute identities — skip the flush
            float4 a = s_sum[tid];
            float4 m = s_max[tid];
#pragma unroll
            for (int k = 1; k < 4; ++k) {
                float4 a2 = s_sum[tid + 64 * k];
                float4 m2 = s_max[tid + 64 * k];
                a.x += a2.x; a.y += a2.y; a.z += a2.z; a.w += a2.w;
                m.x = fmaxf(m.x, m2.x); m.y = fmaxf(m.y, m2.y);
                m.z = fmaxf(m.z, m2.z); m.w = fmaxf(m.w, m2.w);
            }
            const int dbase = b * DD + tid * 4;
            atomicAdd(&g_sum[dbase + 0], a.x);
            atomicAdd(&g_sum[dbase + 1], a.y);
            atomicAdd(&g_sum[dbase + 2], a.z);
            atomicAdd(&g_sum[dbase + 3], a.w);
            atomicMax(&g_maxo[dbase + 0], f2o(m.x));
            atomicMax(&g_maxo[dbase + 1], f2o(m.y));
            atomicMax(&g_maxo[dbase + 2], f2o(m.z));
            atomicMax(&g_maxo[dbase + 3], f2o(m.w));
            if (tid == 0) atomicAdd(&g_cnt[b], ctot);
        }
    }

    // Arrival: syncthreads orders every thread's flushes before tid0's acq_rel add.
    __syncthreads();
    __shared__ int s_last;
    if (tid == 0)
        s_last = (arrive_acq_rel(&g_arrived[b]) == NSPLIT - 1);
    __syncthreads();
    if (!s_last) return;

    // Last CTA for this b: accumulators final (acquire above). Write output,
    // reset scratch for the next graph replay.
    {
        const int d = tid;  // 0..255
        float    fsum = __ldcg(&g_sum[b * DD + d]);
        unsigned mo   = __ldcg(&g_maxo[b * DD + d]);
        float    fcnt = __ldcg(&g_cnt[b]);
        out[(size_t)b * (2 * DD) + d]      = o2f(mo);
        out[(size_t)b * (2 * DD) + DD + d] = fsum / fcnt;
        __stcg(&g_sum[b * DD + d], 0.f);
        __stcg(&g_maxo[b * DD + d], 0u);
        if (tid == 0) {
            __stcg(&g_cnt[b], 0.f);
            __stcg(&g_arrived[b], 0);
        }
    }
}

extern "C" void kernel_launch(void* const* d_in, const int* in_sizes, int n_in,
                              void* d_out, int out_size) {
    const float* feats = (const float*)d_in[0];
    const float* mask  = (const float*)d_in[1];
    float* out = (float*)d_out;

    dim3 grid(NSPLIT, BB);
    pool_strided6<<<grid, 256>>>(feats, mask, out);
}